// round 1
// baseline (speedup 1.0000x reference)
#include <cuda_runtime.h>

#define TOKENS 65536
#define DIM 512

// Scratch (allocation-free rule: __device__ globals). 4 x 128 MiB fp32.
__device__ float g_q[(size_t)TOKENS * DIM];
__device__ float g_k[(size_t)TOKENS * DIM];
__device__ float g_v[(size_t)TOKENS * DIM];
__device__ float g_y[(size_t)TOKENS * DIM];

// ---------------------------------------------------------------------------
// SGEMM: C[M,512] = A[M,512] @ W[512,512]^T + bias   (nn.Linear semantics)
// Both operands are K-contiguous (NT gemm). 128x128x8 tiles, 8x8 microtile.
// ---------------------------------------------------------------------------
__global__ __launch_bounds__(256)
void sgemm_bias_kernel(const float* __restrict__ A, const float* __restrict__ W,
                       const float* __restrict__ bias, float* __restrict__ C) {
    __shared__ float As[8][132];   // transposed A tile, padded (132*4 % 16 == 0)
    __shared__ float Bs[8][132];   // transposed W tile

    const int tid  = threadIdx.x;
    const int brow = blockIdx.y * 128;
    const int bcol = blockIdx.x * 128;
    const int ty   = tid >> 4;       // 0..15
    const int tx   = tid & 15;       // 0..15
    const int lr   = tid >> 1;       // 0..127 (load row)
    const int lc   = (tid & 1) * 4;  // 0 or 4 (load col group)

    const float* Ag = A + (size_t)(brow + lr) * DIM + lc;
    const float* Wg = W + (size_t)(bcol + lr) * DIM + lc;

    float acc[8][8];
#pragma unroll
    for (int i = 0; i < 8; i++)
#pragma unroll
        for (int j = 0; j < 8; j++) acc[i][j] = 0.f;

    for (int k0 = 0; k0 < DIM; k0 += 8) {
        float4 av = *(const float4*)(Ag + k0);
        float4 wv = *(const float4*)(Wg + k0);
        As[lc + 0][lr] = av.x; As[lc + 1][lr] = av.y;
        As[lc + 2][lr] = av.z; As[lc + 3][lr] = av.w;
        Bs[lc + 0][lr] = wv.x; Bs[lc + 1][lr] = wv.y;
        Bs[lc + 2][lr] = wv.z; Bs[lc + 3][lr] = wv.w;
        __syncthreads();

#pragma unroll
        for (int k = 0; k < 8; k++) {
            float a[8], b[8];
            *(float4*)&a[0] = *(const float4*)&As[k][ty * 8];
            *(float4*)&a[4] = *(const float4*)&As[k][ty * 8 + 4];
            *(float4*)&b[0] = *(const float4*)&Bs[k][tx * 8];
            *(float4*)&b[4] = *(const float4*)&Bs[k][tx * 8 + 4];
#pragma unroll
            for (int i = 0; i < 8; i++)
#pragma unroll
                for (int j = 0; j < 8; j++) acc[i][j] += a[i] * b[j];
        }
        __syncthreads();
    }

    float bv[8];
#pragma unroll
    for (int j = 0; j < 8; j++) bv[j] = bias[bcol + tx * 8 + j];

#pragma unroll
    for (int i = 0; i < 8; i++) {
        float* Cp = C + (size_t)(brow + ty * 8 + i) * DIM + bcol + tx * 8;
        float4 o0 = make_float4(acc[i][0] + bv[0], acc[i][1] + bv[1],
                                acc[i][2] + bv[2], acc[i][3] + bv[3]);
        float4 o1 = make_float4(acc[i][4] + bv[4], acc[i][5] + bv[5],
                                acc[i][6] + bv[6], acc[i][7] + bv[7]);
        *(float4*)(Cp + 0) = o0;
        *(float4*)(Cp + 4) = o1;
    }
}

// ---------------------------------------------------------------------------
// Micro-attention: one block per (sequence, head). L=32, E=64, H=8.
// Token-major buffers: seq members are rows t0 + j*stride.
//   stage 1: stride = 8   (vary j,  fixed b,gi,p), ostride = 256
//   stage 2: stride = 256 (vary gi, fixed b,j, p), ostride = 8
// ---------------------------------------------------------------------------
__global__ __launch_bounds__(256)
void attn_kernel(const float* __restrict__ Q, const float* __restrict__ K,
                 const float* __restrict__ V, float* __restrict__ Y,
                 int stride, int ostride) {
    __shared__ float Qs[32][68];   // 68*4 % 16 == 0 -> float4 OK, no 64-stride conflicts
    __shared__ float Ks[32][68];
    __shared__ float Vs[32][68];
    __shared__ float Ss[32][33];

    const int tid = threadIdx.x;
    const int bid = blockIdx.x;
    const int s   = bid >> 3;     // sequence id, 0..2047
    const int h   = bid & 7;      // head
    const int b   = s >> 8;
    const int u   = (s >> 3) & 31;
    const int p   = s & 7;
    const int t0  = b * 8192 + u * ostride + p;

    // Cooperative gather of Q/K/V [32 x 64] for this head.
#pragma unroll
    for (int it = 0; it < 2; it++) {
        int idx = tid + it * 256;
        int row = idx >> 4;
        int c4  = (idx & 15) * 4;
        size_t g = (size_t)(t0 + row * stride) * DIM + h * 64 + c4;
        *(float4*)&Qs[row][c4] = *(const float4*)(Q + g);
        *(float4*)&Ks[row][c4] = *(const float4*)(K + g);
        *(float4*)&Vs[row][c4] = *(const float4*)(V + g);
    }
    __syncthreads();

    const int i = tid >> 3;   // query row 0..31 (8 threads per row)

    // scores[i][j] = (Q[i] . K[j]) / sqrt(64)
    {
        const int j0 = (tid & 7) * 4;
        float sc0 = 0.f, sc1 = 0.f, sc2 = 0.f, sc3 = 0.f;
#pragma unroll
        for (int k = 0; k < 64; k++) {
            float qv = Qs[i][k];
            sc0 += qv * Ks[j0 + 0][k];
            sc1 += qv * Ks[j0 + 1][k];
            sc2 += qv * Ks[j0 + 2][k];
            sc3 += qv * Ks[j0 + 3][k];
        }
        Ss[i][j0 + 0] = sc0 * 0.125f;
        Ss[i][j0 + 1] = sc1 * 0.125f;
        Ss[i][j0 + 2] = sc2 * 0.125f;
        Ss[i][j0 + 3] = sc3 * 0.125f;
    }
    __syncthreads();

    // softmax over j (one thread per row; tiny)
    if (tid < 32) {
        float m = -1e30f;
#pragma unroll
        for (int j = 0; j < 32; j++) m = fmaxf(m, Ss[tid][j]);
        float sum = 0.f;
#pragma unroll
        for (int j = 0; j < 32; j++) {
            float e = expf(Ss[tid][j] - m);
            Ss[tid][j] = e;
            sum += e;
        }
        float inv = 1.f / sum;
#pragma unroll
        for (int j = 0; j < 32; j++) Ss[tid][j] *= inv;
    }
    __syncthreads();

    // O[i][e] = sum_j P[i][j] * V[j][e]
    {
        const int e0 = (tid & 7) * 8;
        float o[8] = {0.f, 0.f, 0.f, 0.f, 0.f, 0.f, 0.f, 0.f};
#pragma unroll
        for (int j = 0; j < 32; j++) {
            float pr = Ss[i][j];
#pragma unroll
            for (int c = 0; c < 8; c++) o[c] += pr * Vs[j][e0 + c];
        }
        float* Yp = Y + (size_t)(t0 + i * stride) * DIM + h * 64 + e0;
        *(float4*)(Yp + 0) = make_float4(o[0], o[1], o[2], o[3]);
        *(float4*)(Yp + 4) = make_float4(o[4], o[5], o[6], o[7]);
    }
}

// ---------------------------------------------------------------------------
// Launch: 7 GEMMs + 2 attention kernels, all token-major, permutations folded
// into attention row indexing. Final GEMM writes d_out directly.
// ---------------------------------------------------------------------------
extern "C" void kernel_launch(void* const* d_in, const int* in_sizes, int n_in,
                              void* d_out, int out_size) {
    const float* x   = (const float*)d_in[0];
    const float* q1w = (const float*)d_in[1];
    const float* q1b = (const float*)d_in[2];
    const float* k1w = (const float*)d_in[3];
    const float* k1b = (const float*)d_in[4];
    const float* v1w = (const float*)d_in[5];
    const float* v1b = (const float*)d_in[6];
    const float* q2w = (const float*)d_in[7];
    const float* q2b = (const float*)d_in[8];
    const float* k2w = (const float*)d_in[9];
    const float* k2b = (const float*)d_in[10];
    const float* v2w = (const float*)d_in[11];
    const float* v2b = (const float*)d_in[12];
    const float* ow  = (const float*)d_in[13];
    const float* ob  = (const float*)d_in[14];
    float* out = (float*)d_out;

    float *Qb, *Kb, *Vb, *Yb;
    cudaGetSymbolAddress((void**)&Qb, g_q);
    cudaGetSymbolAddress((void**)&Kb, g_k);
    cudaGetSymbolAddress((void**)&Vb, g_v);
    cudaGetSymbolAddress((void**)&Yb, g_y);

    dim3 ggrid(DIM / 128, TOKENS / 128);

    // stage 1 projections
    sgemm_bias_kernel<<<ggrid, 256>>>(x, q1w, q1b, Qb);
    sgemm_bias_kernel<<<ggrid, 256>>>(x, k1w, k1b, Kb);
    sgemm_bias_kernel<<<ggrid, 256>>>(x, v1w, v1b, Vb);
    // stage 1 attention: inner-group (stride 8)
    attn_kernel<<<16384, 256>>>(Qb, Kb, Vb, Yb, 8, 256);
    // stage 2 projections
    sgemm_bias_kernel<<<ggrid, 256>>>(Yb, q2w, q2b, Qb);
    sgemm_bias_kernel<<<ggrid, 256>>>(Yb, k2w, k2b, Kb);
    sgemm_bias_kernel<<<ggrid, 256>>>(Yb, v2w, v2b, Vb);
    // stage 2 attention: inter-group (stride 256)
    attn_kernel<<<16384, 256>>>(Qb, Kb, Vb, Yb, 256, 8);
    // output projection -> d_out (layout matches token-major exactly)
    sgemm_bias_kernel<<<ggrid, 256>>>(Yb, ow, ob, out);
}

// round 4
// speedup vs baseline: 2.5865x; 2.5865x over previous
#include <cuda_runtime.h>
#include <cuda_fp16.h>
#include <cstdint>

#define TOKENS 65536
#define DIM 512

// ---------------------------------------------------------------------------
// Device scratch (allocation-free rule)
// ---------------------------------------------------------------------------
__device__ float  g_q[(size_t)TOKENS * DIM];
__device__ float  g_k[(size_t)TOKENS * DIM];
__device__ float  g_v[(size_t)TOKENS * DIM];
__device__ __half g_ahi[(size_t)TOKENS * DIM];
__device__ __half g_alo[(size_t)TOKENS * DIM];
__device__ __half g_whi[7u * DIM * DIM];
__device__ __half g_wlo[7u * DIM * DIM];

// ---------------------------------------------------------------------------
// PTX helpers (baseline PTX only: works on sm_100 non-'a' target)
// ---------------------------------------------------------------------------
__device__ __forceinline__ uint32_t smem_u32(const void* p) {
    uint32_t a;
    asm("{ .reg .u64 t; cvta.to.shared.u64 t, %1; cvt.u32.u64 %0, t; }" : "=r"(a) : "l"(p));
    return a;
}

#define CP_ASYNC16(dst, src)                                                   \
    asm volatile("cp.async.ca.shared.global [%0], [%1], 16;"                   \
                 :: "r"(dst), "l"(src) : "memory")
#define CP_COMMIT() asm volatile("cp.async.commit_group;" ::: "memory")
#define CP_WAIT(n)  asm volatile("cp.async.wait_group %0;" :: "n"(n) : "memory")

__device__ __forceinline__ void ldsm_x4(uint32_t* r, uint32_t addr) {
    asm volatile("ldmatrix.sync.aligned.m8n8.x4.shared.b16 {%0,%1,%2,%3}, [%4];"
                 : "=r"(r[0]), "=r"(r[1]), "=r"(r[2]), "=r"(r[3]) : "r"(addr));
}
__device__ __forceinline__ void ldsm_x2(uint32_t* r, uint32_t addr) {
    asm volatile("ldmatrix.sync.aligned.m8n8.x2.shared.b16 {%0,%1}, [%2];"
                 : "=r"(r[0]), "=r"(r[1]) : "r"(addr));
}
__device__ __forceinline__ void mma16816(float* c, const uint32_t* a, const uint32_t* b) {
    asm volatile("mma.sync.aligned.m16n8k16.row.col.f32.f16.f16.f32 "
                 "{%0,%1,%2,%3}, {%4,%5,%6,%7}, {%8,%9}, {%0,%1,%2,%3};"
                 : "+f"(c[0]), "+f"(c[1]), "+f"(c[2]), "+f"(c[3])
                 : "r"(a[0]), "r"(a[1]), "r"(a[2]), "r"(a[3]), "r"(b[0]), "r"(b[1]));
}

// ---------------------------------------------------------------------------
// Split fp32 -> fp16 hi/lo
// ---------------------------------------------------------------------------
__global__ __launch_bounds__(256)
void split_kernel(const float* __restrict__ in, __half* __restrict__ hi,
                  __half* __restrict__ lo, int n4) {
    int i = blockIdx.x * 256 + threadIdx.x;
    if (i >= n4) return;
    float4 v = ((const float4*)in)[i];
    __half h0 = __float2half_rn(v.x), h1 = __float2half_rn(v.y);
    __half h2 = __float2half_rn(v.z), h3 = __float2half_rn(v.w);
    __half l0 = __float2half_rn(v.x - __half2float(h0));
    __half l1 = __float2half_rn(v.y - __half2float(h1));
    __half l2 = __float2half_rn(v.z - __half2float(h2));
    __half l3 = __float2half_rn(v.w - __half2float(h3));
    __half2* hp = (__half2*)hi + (size_t)i * 2;
    __half2* lp = (__half2*)lo + (size_t)i * 2;
    hp[0] = __halves2half2(h0, h1); hp[1] = __halves2half2(h2, h3);
    lp[0] = __halves2half2(l0, l1); lp[1] = __halves2half2(l2, l3);
}

// ---------------------------------------------------------------------------
// HMMA GEMM: C[65536,512] = A@W^T + bias via 3 fp16-split pairings
//   Ahi*Whi + Alo*Whi + Ahi*Wlo  (lo*lo dropped, ~2^-22)
// CTA tile 128x128, 8 warps (2x4), warp tile 64x32, K chunks of 32.
// Each chunk loads Ahi/Alo/Whi/Wlo tiles once (cp.async, double buffered);
// MMA phase runs all 3 pairings off the shared tiles.
// smem tile: 128 rows x 32 halfs, row stride 40 halfs (80B) -> conflict-free
// ldmatrix; 4 tiles x 10240B = 40960B/stage, 2 stages = 81920B dynamic.
// ---------------------------------------------------------------------------
#define TILE_B   10240
#define STAGE_B  40960
#define GSMEM_BYTES (2 * STAGE_B)

__global__ __launch_bounds__(256)
void gemm_kernel(const __half* __restrict__ Ahi, const __half* __restrict__ Alo,
                 const __half* __restrict__ Whi, const __half* __restrict__ Wlo,
                 const float* __restrict__ bias, float* __restrict__ C) {
    extern __shared__ char smem[];
    const uint32_t sbase = smem_u32(smem);
    const int tid = threadIdx.x, wid = tid >> 5, lane = tid & 31;
    const int m0 = blockIdx.y * 128, n0 = blockIdx.x * 128;
    const int wm = (wid >> 2) * 64;    // warp row offset in CTA tile
    const int wn = (wid & 3) * 32;     // warp col offset

    const __half* gsrc[4] = {Ahi, Alo, Whi, Wlo};

    // issue cp.async loads for chunk c into stage c&1
    auto issue = [&](int c) {
        const int koff = c * 32;
        const uint32_t stg = sbase + (uint32_t)(c & 1) * STAGE_B;
#pragma unroll
        for (int tl = 0; tl < 4; tl++) {
            const __half* src = gsrc[tl];
            const int rowbase = (tl < 2) ? m0 : n0;
#pragma unroll
            for (int h = 0; h < 2; h++) {
                int chunk = tid + h * 256;          // 0..511
                int r = chunk >> 2, c4 = chunk & 3;
                const __half* g = src + (size_t)(rowbase + r) * DIM + koff + c4 * 8;
                uint32_t d = stg + (uint32_t)tl * TILE_B + r * 80 + c4 * 16;
                CP_ASYNC16(d, (const void*)g);
            }
        }
        CP_COMMIT();
    };

    float acc[4][4][4];
#pragma unroll
    for (int i = 0; i < 4; i++)
#pragma unroll
        for (int j = 0; j < 4; j++)
#pragma unroll
            for (int k = 0; k < 4; k++) acc[i][j][k] = 0.f;

    issue(0);

    // ldmatrix lane address components
    const int a_row = lane & 15;           // + mf*16 + wm
    const int a_kb  = (lane >> 4) * 8;     // k sub-block within 16
    const int b_row = lane & 7;            // + nf*8 + wn
    const int b_kb  = ((lane >> 3) & 1) * 8;

    for (int c = 0; c < 16; c++) {
        if (c + 1 < 16) { issue(c + 1); CP_WAIT(1); }
        else            { CP_WAIT(0); }
        __syncthreads();

        const uint32_t stg = sbase + (uint32_t)(c & 1) * STAGE_B;
        const uint32_t sAh = stg;
        const uint32_t sAl = stg + TILE_B;
        const uint32_t sWh = stg + 2 * TILE_B;
        const uint32_t sWl = stg + 3 * TILE_B;

#pragma unroll
        for (int ks = 0; ks < 2; ks++) {
            const int kb = ks * 16;
            uint32_t ah[4][4], bh[4][2];
            // A-hi fragments (4 m-frags of 16 rows)
#pragma unroll
            for (int mf = 0; mf < 4; mf++)
                ldsm_x4(ah[mf], sAh + (uint32_t)(wm + mf * 16 + a_row) * 80 + (kb + a_kb) * 2);
            // W-hi fragments (4 n-frags of 8 rows)
#pragma unroll
            for (int nf = 0; nf < 4; nf++)
                ldsm_x2(bh[nf], sWh + (uint32_t)(wn + nf * 8 + b_row) * 80 + (kb + b_kb) * 2);
            // pairing 1: Ahi x Whi
#pragma unroll
            for (int mf = 0; mf < 4; mf++)
#pragma unroll
                for (int nf = 0; nf < 4; nf++) mma16816(acc[mf][nf], ah[mf], bh[nf]);
            // pairing 2: Alo x Whi
            {
                uint32_t al[4][4];
#pragma unroll
                for (int mf = 0; mf < 4; mf++)
                    ldsm_x4(al[mf], sAl + (uint32_t)(wm + mf * 16 + a_row) * 80 + (kb + a_kb) * 2);
#pragma unroll
                for (int mf = 0; mf < 4; mf++)
#pragma unroll
                    for (int nf = 0; nf < 4; nf++) mma16816(acc[mf][nf], al[mf], bh[nf]);
            }
            // pairing 3: Ahi x Wlo
            {
                uint32_t bl[4][2];
#pragma unroll
                for (int nf = 0; nf < 4; nf++)
                    ldsm_x2(bl[nf], sWl + (uint32_t)(wn + nf * 8 + b_row) * 80 + (kb + b_kb) * 2);
#pragma unroll
                for (int mf = 0; mf < 4; mf++)
#pragma unroll
                    for (int nf = 0; nf < 4; nf++) mma16816(acc[mf][nf], ah[mf], bl[nf]);
            }
        }
        __syncthreads();
    }

    // Epilogue: bias add, fp32 stores
    const int er = lane >> 2, ec = (lane & 3) * 2;
#pragma unroll
    for (int nf = 0; nf < 4; nf++) {
        const int col = n0 + wn + nf * 8 + ec;
        const float b0 = bias[col], b1 = bias[col + 1];
#pragma unroll
        for (int mf = 0; mf < 4; mf++) {
            const int row = m0 + wm + mf * 16 + er;
            float2 v0 = make_float2(acc[mf][nf][0] + b0, acc[mf][nf][1] + b1);
            float2 v1 = make_float2(acc[mf][nf][2] + b0, acc[mf][nf][3] + b1);
            *(float2*)(C + (size_t)row * DIM + col) = v0;
            *(float2*)(C + (size_t)(row + 8) * DIM + col) = v1;
        }
    }
}

// ---------------------------------------------------------------------------
// Attention: one warp per (seq, head). lane = query row. L=32, E=64.
// Q/scores/output in registers, K/V in per-warp smem (broadcast LDS.128).
// Fused epilogue writes fp16 hi/lo split for the next GEMM stage.
// ---------------------------------------------------------------------------
#define ASMEM_BYTES (4 * 2 * 32 * 68 * 4)

__global__ __launch_bounds__(128)
void attn2_kernel(const float* __restrict__ Q, const float* __restrict__ K,
                  const float* __restrict__ V, __half* __restrict__ Yhi,
                  __half* __restrict__ Ylo, int stride, int ostride) {
    extern __shared__ float ash[];
    const int tid = threadIdx.x;
    const int w = tid >> 5, lane = tid & 31;
    float* Ks = ash + w * (2 * 32 * 68);
    float* Vs = Ks + 32 * 68;

    const int pi = blockIdx.x * 4 + w;
    const int s = pi >> 3, h = pi & 7;
    const int b = s >> 8, u = (s >> 3) & 31, p = s & 7;
    const int t0 = b * 8192 + u * ostride + p;
    const size_t base = (size_t)t0 * DIM + h * 64;

#pragma unroll
    for (int it = 0; it < 16; it++) {
        int idx = lane + it * 32;
        int r = idx >> 4, c4 = (idx & 15) * 4;
        size_t g = base + (size_t)r * stride * DIM + c4;
        *(float4*)(Ks + r * 68 + c4) = *(const float4*)(K + g);
        *(float4*)(Vs + r * 68 + c4) = *(const float4*)(V + g);
    }
    float q[64];
    {
        size_t g = base + (size_t)lane * stride * DIM;
#pragma unroll
        for (int k = 0; k < 16; k++)
            *(float4*)(q + k * 4) = *(const float4*)(Q + g + k * 4);
    }
    __syncwarp();

    float sc[32];
#pragma unroll 2
    for (int j = 0; j < 32; j++) {
        float a0 = 0.f, a1 = 0.f, a2 = 0.f, a3 = 0.f;
#pragma unroll
        for (int k = 0; k < 16; k++) {
            float4 kv = *(const float4*)(Ks + j * 68 + k * 4);
            a0 += q[k * 4 + 0] * kv.x; a1 += q[k * 4 + 1] * kv.y;
            a2 += q[k * 4 + 2] * kv.z; a3 += q[k * 4 + 3] * kv.w;
        }
        sc[j] = (a0 + a1 + a2 + a3) * 0.125f;
    }
    float m = sc[0];
#pragma unroll
    for (int j = 1; j < 32; j++) m = fmaxf(m, sc[j]);
    float sum = 0.f;
#pragma unroll
    for (int j = 0; j < 32; j++) { sc[j] = __expf(sc[j] - m); sum += sc[j]; }
    float inv = 1.f / sum;
#pragma unroll
    for (int j = 0; j < 32; j++) sc[j] *= inv;

    float o[64];
#pragma unroll
    for (int k = 0; k < 64; k++) o[k] = 0.f;
#pragma unroll 2
    for (int j = 0; j < 32; j++) {
        float pj = sc[j];
#pragma unroll
        for (int k = 0; k < 16; k++) {
            float4 vv = *(const float4*)(Vs + j * 68 + k * 4);
            o[k * 4 + 0] += pj * vv.x; o[k * 4 + 1] += pj * vv.y;
            o[k * 4 + 2] += pj * vv.z; o[k * 4 + 3] += pj * vv.w;
        }
    }
    size_t og = base + (size_t)lane * stride * DIM;
#pragma unroll
    for (int k = 0; k < 16; k++) {
        float v0 = o[k * 4 + 0], v1 = o[k * 4 + 1], v2 = o[k * 4 + 2], v3 = o[k * 4 + 3];
        __half h0 = __float2half_rn(v0), h1 = __float2half_rn(v1);
        __half h2 = __float2half_rn(v2), h3 = __float2half_rn(v3);
        __half l0 = __float2half_rn(v0 - __half2float(h0));
        __half l1 = __float2half_rn(v1 - __half2float(h1));
        __half l2 = __float2half_rn(v2 - __half2float(h2));
        __half l3 = __float2half_rn(v3 - __half2float(h3));
        __half2 ha = __halves2half2(h0, h1), hb = __halves2half2(h2, h3);
        __half2 la = __halves2half2(l0, l1), lb = __halves2half2(l2, l3);
        uint2 hu, lu;
        hu.x = *(uint32_t*)&ha; hu.y = *(uint32_t*)&hb;
        lu.x = *(uint32_t*)&la; lu.y = *(uint32_t*)&lb;
        *(uint2*)(Yhi + og + k * 4) = hu;
        *(uint2*)(Ylo + og + k * 4) = lu;
    }
}

// ---------------------------------------------------------------------------
// Host launch
// ---------------------------------------------------------------------------
extern "C" void kernel_launch(void* const* d_in, const int* in_sizes, int n_in,
                              void* d_out, int out_size) {
    const float* x = (const float*)d_in[0];
    const float* wsrc[7] = {(const float*)d_in[1], (const float*)d_in[3],
                            (const float*)d_in[5], (const float*)d_in[7],
                            (const float*)d_in[9], (const float*)d_in[11],
                            (const float*)d_in[13]};
    const float* bsrc[7] = {(const float*)d_in[2], (const float*)d_in[4],
                            (const float*)d_in[6], (const float*)d_in[8],
                            (const float*)d_in[10], (const float*)d_in[12],
                            (const float*)d_in[14]};
    float* out = (float*)d_out;

    float *Qb, *Kb, *Vb;
    __half *Ahi, *Alo, *Whi, *Wlo;
    cudaGetSymbolAddress((void**)&Qb, g_q);
    cudaGetSymbolAddress((void**)&Kb, g_k);
    cudaGetSymbolAddress((void**)&Vb, g_v);
    cudaGetSymbolAddress((void**)&Ahi, g_ahi);
    cudaGetSymbolAddress((void**)&Alo, g_alo);
    cudaGetSymbolAddress((void**)&Whi, g_whi);
    cudaGetSymbolAddress((void**)&Wlo, g_wlo);

    cudaFuncSetAttribute(gemm_kernel, cudaFuncAttributeMaxDynamicSharedMemorySize, GSMEM_BYTES);
    cudaFuncSetAttribute(attn2_kernel, cudaFuncAttributeMaxDynamicSharedMemorySize, ASMEM_BYTES);

    // splits
    for (int i = 0; i < 7; i++)
        split_kernel<<<DIM * DIM / 4 / 256, 256>>>(
            wsrc[i], Whi + (size_t)i * DIM * DIM, Wlo + (size_t)i * DIM * DIM, DIM * DIM / 4);
    split_kernel<<<TOKENS * DIM / 4 / 256, 256>>>(x, Ahi, Alo, TOKENS * DIM / 4);

    dim3 ggrid(DIM / 128, TOKENS / 128);
    // stage 1 projections
    gemm_kernel<<<ggrid, 256, GSMEM_BYTES>>>(Ahi, Alo, Whi + 0 * DIM * DIM, Wlo + 0 * DIM * DIM, bsrc[0], Qb);
    gemm_kernel<<<ggrid, 256, GSMEM_BYTES>>>(Ahi, Alo, Whi + 1 * DIM * DIM, Wlo + 1 * DIM * DIM, bsrc[1], Kb);
    gemm_kernel<<<ggrid, 256, GSMEM_BYTES>>>(Ahi, Alo, Whi + 2 * DIM * DIM, Wlo + 2 * DIM * DIM, bsrc[2], Vb);
    // stage 1 attention (stride 8), writes split input for stage 2
    attn2_kernel<<<4096, 128, ASMEM_BYTES>>>(Qb, Kb, Vb, Ahi, Alo, 8, 256);
    // stage 2 projections
    gemm_kernel<<<ggrid, 256, GSMEM_BYTES>>>(Ahi, Alo, Whi + 3 * DIM * DIM, Wlo + 3 * DIM * DIM, bsrc[3], Qb);
    gemm_kernel<<<ggrid, 256, GSMEM_BYTES>>>(Ahi, Alo, Whi + 4 * DIM * DIM, Wlo + 4 * DIM * DIM, bsrc[4], Kb);
    gemm_kernel<<<ggrid, 256, GSMEM_BYTES>>>(Ahi, Alo, Whi + 5 * DIM * DIM, Wlo + 5 * DIM * DIM, bsrc[5], Vb);
    // stage 2 attention (stride 256)
    attn2_kernel<<<4096, 128, ASMEM_BYTES>>>(Qb, Kb, Vb, Ahi, Alo, 256, 8);
    // output projection -> d_out
    gemm_kernel<<<ggrid, 256, GSMEM_BYTES>>>(Ahi, Alo, Whi + 6 * DIM * DIM, Wlo + 6 * DIM * DIM, bsrc[6], out);
}

// round 5
// speedup vs baseline: 2.6140x; 1.0106x over previous
#include <cuda_runtime.h>
#include <cuda_fp16.h>
#include <cstdint>

#define TOKENS 65536
#define DIM 512

// ---------------------------------------------------------------------------
// Device scratch (allocation-free rule)
// ---------------------------------------------------------------------------
__device__ float  g_q[(size_t)TOKENS * DIM];
__device__ float  g_k[(size_t)TOKENS * DIM];
__device__ float  g_v[(size_t)TOKENS * DIM];
__device__ __half g_ahi[(size_t)TOKENS * DIM];
__device__ __half g_alo[(size_t)TOKENS * DIM];
__device__ __half g_whi[7u * DIM * DIM];
__device__ __half g_wlo[7u * DIM * DIM];

// ---------------------------------------------------------------------------
// PTX helpers (baseline PTX only: sm_100 non-'a' target)
// ---------------------------------------------------------------------------
__device__ __forceinline__ uint32_t smem_u32(const void* p) {
    uint32_t a;
    asm("{ .reg .u64 t; cvta.to.shared.u64 t, %1; cvt.u32.u64 %0, t; }" : "=r"(a) : "l"(p));
    return a;
}

#define CP_ASYNC16(dst, src)                                                   \
    asm volatile("cp.async.ca.shared.global [%0], [%1], 16;"                   \
                 :: "r"(dst), "l"(src) : "memory")
#define CP_COMMIT() asm volatile("cp.async.commit_group;" ::: "memory")
#define CP_WAIT(n)  asm volatile("cp.async.wait_group %0;" :: "n"(n) : "memory")

__device__ __forceinline__ void ldsm_x4(uint32_t* r, uint32_t addr) {
    asm volatile("ldmatrix.sync.aligned.m8n8.x4.shared.b16 {%0,%1,%2,%3}, [%4];"
                 : "=r"(r[0]), "=r"(r[1]), "=r"(r[2]), "=r"(r[3]) : "r"(addr));
}
__device__ __forceinline__ void ldsm_x2(uint32_t* r, uint32_t addr) {
    asm volatile("ldmatrix.sync.aligned.m8n8.x2.shared.b16 {%0,%1}, [%2];"
                 : "=r"(r[0]), "=r"(r[1]) : "r"(addr));
}
__device__ __forceinline__ void mma16816(float* c, const uint32_t* a, const uint32_t* b) {
    asm volatile("mma.sync.aligned.m16n8k16.row.col.f32.f16.f16.f32 "
                 "{%0,%1,%2,%3}, {%4,%5,%6,%7}, {%8,%9}, {%0,%1,%2,%3};"
                 : "+f"(c[0]), "+f"(c[1]), "+f"(c[2]), "+f"(c[3])
                 : "r"(a[0]), "r"(a[1]), "r"(a[2]), "r"(a[3]), "r"(b[0]), "r"(b[1]));
}

// ---------------------------------------------------------------------------
// Fused split: one launch handles 7 weight matrices + the activation tensor.
// Blocks [0, 1792): weights (256 blocks each). Blocks [1792, ...): x.
// ---------------------------------------------------------------------------
__device__ __forceinline__ void split4(const float* __restrict__ in, __half* __restrict__ hi,
                                       __half* __restrict__ lo, size_t i) {
    float4 v = ((const float4*)in)[i];
    __half h0 = __float2half_rn(v.x), h1 = __float2half_rn(v.y);
    __half h2 = __float2half_rn(v.z), h3 = __float2half_rn(v.w);
    __half l0 = __float2half_rn(v.x - __half2float(h0));
    __half l1 = __float2half_rn(v.y - __half2float(h1));
    __half l2 = __float2half_rn(v.z - __half2float(h2));
    __half l3 = __float2half_rn(v.w - __half2float(h3));
    __half2* hp = (__half2*)hi + i * 2;
    __half2* lp = (__half2*)lo + i * 2;
    hp[0] = __halves2half2(h0, h1); hp[1] = __halves2half2(h2, h3);
    lp[0] = __halves2half2(l0, l1); lp[1] = __halves2half2(l2, l3);
}

#define WSPLIT_BLOCKS 1792   // 7 * (512*512/4/256)

__global__ __launch_bounds__(256)
void split_all_kernel(const float* __restrict__ x,
                      const float* __restrict__ w0, const float* __restrict__ w1,
                      const float* __restrict__ w2, const float* __restrict__ w3,
                      const float* __restrict__ w4, const float* __restrict__ w5,
                      const float* __restrict__ w6,
                      __half* __restrict__ Ahi, __half* __restrict__ Alo,
                      __half* __restrict__ Whi, __half* __restrict__ Wlo) {
    const int bid = blockIdx.x;
    if (bid < WSPLIT_BLOCKS) {
        const int wi = bid >> 8;
        const float* src;
        switch (wi) {
            case 0: src = w0; break; case 1: src = w1; break;
            case 2: src = w2; break; case 3: src = w3; break;
            case 4: src = w4; break; case 5: src = w5; break;
            default: src = w6; break;
        }
        size_t i = (size_t)(bid & 255) * 256 + threadIdx.x;
        split4(src, Whi + (size_t)wi * DIM * DIM, Wlo + (size_t)wi * DIM * DIM, i);
    } else {
        size_t i = (size_t)(bid - WSPLIT_BLOCKS) * 256 + threadIdx.x;
        split4(x, Ahi, Alo, i);
    }
}

// ---------------------------------------------------------------------------
// HMMA GEMM: C[65536,512] = A@W^T + bias via 3 fp16-split pairings
//   Ahi*Whi + Alo*Whi + Ahi*Wlo  (lo*lo dropped, ~2^-22)
// CTA tile 128x128, 8 warps (2x4), warp tile 64x32, K chunks of 32.
// 2-stage cp.async double buffering; __launch_bounds__(256, 2) forces
// <=128 regs so 2 CTAs/SM co-reside (smem 2x80KB = 160KB < 228KB), hiding
// the per-chunk barrier + cp.async drains.
// ---------------------------------------------------------------------------
#define TILE_B   10240
#define STAGE_B  40960
#define GSMEM_BYTES (2 * STAGE_B)

__global__ __launch_bounds__(256, 2)
void gemm_kernel(const __half* __restrict__ Ahi, const __half* __restrict__ Alo,
                 const __half* __restrict__ Whi, const __half* __restrict__ Wlo,
                 const float* __restrict__ bias, float* __restrict__ C) {
    extern __shared__ char smem[];
    const uint32_t sbase = smem_u32(smem);
    const int tid = threadIdx.x, wid = tid >> 5, lane = tid & 31;
    const int m0 = blockIdx.y * 128, n0 = blockIdx.x * 128;
    const int wm = (wid >> 2) * 64;
    const int wn = (wid & 3) * 32;

    const __half* gsrc[4] = {Ahi, Alo, Whi, Wlo};

    auto issue = [&](int c) {
        const int koff = c * 32;
        const uint32_t stg = sbase + (uint32_t)(c & 1) * STAGE_B;
#pragma unroll
        for (int tl = 0; tl < 4; tl++) {
            const __half* src = gsrc[tl];
            const int rowbase = (tl < 2) ? m0 : n0;
#pragma unroll
            for (int h = 0; h < 2; h++) {
                int chunk = tid + h * 256;
                int r = chunk >> 2, c4 = chunk & 3;
                const __half* g = src + (size_t)(rowbase + r) * DIM + koff + c4 * 8;
                uint32_t d = stg + (uint32_t)tl * TILE_B + r * 80 + c4 * 16;
                CP_ASYNC16(d, (const void*)g);
            }
        }
        CP_COMMIT();
    };

    float acc[4][4][4];
#pragma unroll
    for (int i = 0; i < 4; i++)
#pragma unroll
        for (int j = 0; j < 4; j++)
#pragma unroll
            for (int k = 0; k < 4; k++) acc[i][j][k] = 0.f;

    issue(0);

    const int a_row = lane & 15;
    const int a_kb  = (lane >> 4) * 8;
    const int b_row = lane & 7;
    const int b_kb  = ((lane >> 3) & 1) * 8;

    for (int c = 0; c < 16; c++) {
        if (c + 1 < 16) { issue(c + 1); CP_WAIT(1); }
        else            { CP_WAIT(0); }
        __syncthreads();

        const uint32_t stg = sbase + (uint32_t)(c & 1) * STAGE_B;
        const uint32_t sAh = stg;
        const uint32_t sAl = stg + TILE_B;
        const uint32_t sWh = stg + 2 * TILE_B;
        const uint32_t sWl = stg + 3 * TILE_B;

#pragma unroll
        for (int ks = 0; ks < 2; ks++) {
            const int kb = ks * 16;
            uint32_t ah[4][4], bh[4][2];
#pragma unroll
            for (int mf = 0; mf < 4; mf++)
                ldsm_x4(ah[mf], sAh + (uint32_t)(wm + mf * 16 + a_row) * 80 + (kb + a_kb) * 2);
#pragma unroll
            for (int nf = 0; nf < 4; nf++)
                ldsm_x2(bh[nf], sWh + (uint32_t)(wn + nf * 8 + b_row) * 80 + (kb + b_kb) * 2);
            // pairing 1: Ahi x Whi
#pragma unroll
            for (int mf = 0; mf < 4; mf++)
#pragma unroll
                for (int nf = 0; nf < 4; nf++) mma16816(acc[mf][nf], ah[mf], bh[nf]);
            // pairing 2: Alo x Whi
            {
                uint32_t al[4][4];
#pragma unroll
                for (int mf = 0; mf < 4; mf++)
                    ldsm_x4(al[mf], sAl + (uint32_t)(wm + mf * 16 + a_row) * 80 + (kb + a_kb) * 2);
#pragma unroll
                for (int mf = 0; mf < 4; mf++)
#pragma unroll
                    for (int nf = 0; nf < 4; nf++) mma16816(acc[mf][nf], al[mf], bh[nf]);
            }
            // pairing 3: Ahi x Wlo
            {
                uint32_t bl[4][2];
#pragma unroll
                for (int nf = 0; nf < 4; nf++)
                    ldsm_x2(bl[nf], sWl + (uint32_t)(wn + nf * 8 + b_row) * 80 + (kb + b_kb) * 2);
#pragma unroll
                for (int mf = 0; mf < 4; mf++)
#pragma unroll
                    for (int nf = 0; nf < 4; nf++) mma16816(acc[mf][nf], ah[mf], bl[nf]);
            }
        }
        __syncthreads();
    }

    const int er = lane >> 2, ec = (lane & 3) * 2;
#pragma unroll
    for (int nf = 0; nf < 4; nf++) {
        const int col = n0 + wn + nf * 8 + ec;
        const float b0 = bias[col], b1 = bias[col + 1];
#pragma unroll
        for (int mf = 0; mf < 4; mf++) {
            const int row = m0 + wm + mf * 16 + er;
            float2 v0 = make_float2(acc[mf][nf][0] + b0, acc[mf][nf][1] + b1);
            float2 v1 = make_float2(acc[mf][nf][2] + b0, acc[mf][nf][3] + b1);
            *(float2*)(C + (size_t)row * DIM + col) = v0;
            *(float2*)(C + (size_t)(row + 8) * DIM + col) = v1;
        }
    }
}

// ---------------------------------------------------------------------------
// Attention: one warp per (seq, head). lane = query row. L=32, E=64.
// Fused epilogue writes fp16 hi/lo split for the next GEMM stage.
// ---------------------------------------------------------------------------
#define ASMEM_BYTES (4 * 2 * 32 * 68 * 4)

__global__ __launch_bounds__(128)
void attn2_kernel(const float* __restrict__ Q, const float* __restrict__ K,
                  const float* __restrict__ V, __half* __restrict__ Yhi,
                  __half* __restrict__ Ylo, int stride, int ostride) {
    extern __shared__ float ash[];
    const int tid = threadIdx.x;
    const int w = tid >> 5, lane = tid & 31;
    float* Ks = ash + w * (2 * 32 * 68);
    float* Vs = Ks + 32 * 68;

    const int pi = blockIdx.x * 4 + w;
    const int s = pi >> 3, h = pi & 7;
    const int b = s >> 8, u = (s >> 3) & 31, p = s & 7;
    const int t0 = b * 8192 + u * ostride + p;
    const size_t base = (size_t)t0 * DIM + h * 64;

#pragma unroll
    for (int it = 0; it < 16; it++) {
        int idx = lane + it * 32;
        int r = idx >> 4, c4 = (idx & 15) * 4;
        size_t g = base + (size_t)r * stride * DIM + c4;
        *(float4*)(Ks + r * 68 + c4) = *(const float4*)(K + g);
        *(float4*)(Vs + r * 68 + c4) = *(const float4*)(V + g);
    }
    float q[64];
    {
        size_t g = base + (size_t)lane * stride * DIM;
#pragma unroll
        for (int k = 0; k < 16; k++)
            *(float4*)(q + k * 4) = *(const float4*)(Q + g + k * 4);
    }
    __syncwarp();

    float sc[32];
#pragma unroll 2
    for (int j = 0; j < 32; j++) {
        float a0 = 0.f, a1 = 0.f, a2 = 0.f, a3 = 0.f;
#pragma unroll
        for (int k = 0; k < 16; k++) {
            float4 kv = *(const float4*)(Ks + j * 68 + k * 4);
            a0 += q[k * 4 + 0] * kv.x; a1 += q[k * 4 + 1] * kv.y;
            a2 += q[k * 4 + 2] * kv.z; a3 += q[k * 4 + 3] * kv.w;
        }
        sc[j] = (a0 + a1 + a2 + a3) * 0.125f;
    }
    float m = sc[0];
#pragma unroll
    for (int j = 1; j < 32; j++) m = fmaxf(m, sc[j]);
    float sum = 0.f;
#pragma unroll
    for (int j = 0; j < 32; j++) { sc[j] = __expf(sc[j] - m); sum += sc[j]; }
    float inv = 1.f / sum;
#pragma unroll
    for (int j = 0; j < 32; j++) sc[j] *= inv;

    float o[64];
#pragma unroll
    for (int k = 0; k < 64; k++) o[k] = 0.f;
#pragma unroll 2
    for (int j = 0; j < 32; j++) {
        float pj = sc[j];
#pragma unroll
        for (int k = 0; k < 16; k++) {
            float4 vv = *(const float4*)(Vs + j * 68 + k * 4);
            o[k * 4 + 0] += pj * vv.x; o[k * 4 + 1] += pj * vv.y;
            o[k * 4 + 2] += pj * vv.z; o[k * 4 + 3] += pj * vv.w;
        }
    }
    size_t og = base + (size_t)lane * stride * DIM;
#pragma unroll
    for (int k = 0; k < 16; k++) {
        float v0 = o[k * 4 + 0], v1 = o[k * 4 + 1], v2 = o[k * 4 + 2], v3 = o[k * 4 + 3];
        __half h0 = __float2half_rn(v0), h1 = __float2half_rn(v1);
        __half h2 = __float2half_rn(v2), h3 = __float2half_rn(v3);
        __half l0 = __float2half_rn(v0 - __half2float(h0));
        __half l1 = __float2half_rn(v1 - __half2float(h1));
        __half l2 = __float2half_rn(v2 - __half2float(h2));
        __half l3 = __float2half_rn(v3 - __half2float(h3));
        __half2 ha = __halves2half2(h0, h1), hb = __halves2half2(h2, h3);
        __half2 la = __halves2half2(l0, l1), lb = __halves2half2(l2, l3);
        uint2 hu, lu;
        hu.x = *(uint32_t*)&ha; hu.y = *(uint32_t*)&hb;
        lu.x = *(uint32_t*)&la; lu.y = *(uint32_t*)&lb;
        *(uint2*)(Yhi + og + k * 4) = hu;
        *(uint2*)(Ylo + og + k * 4) = lu;
    }
}

// ---------------------------------------------------------------------------
// Host launch. Order matters for ncu -s 5: [split_all, g1, g2, g3, attn1,
// g4(stage-2 Q) <- profiled, g5, g6, attn2, g7].
// ---------------------------------------------------------------------------
extern "C" void kernel_launch(void* const* d_in, const int* in_sizes, int n_in,
                              void* d_out, int out_size) {
    const float* x = (const float*)d_in[0];
    const float* wsrc[7] = {(const float*)d_in[1], (const float*)d_in[3],
                            (const float*)d_in[5], (const float*)d_in[7],
                            (const float*)d_in[9], (const float*)d_in[11],
                            (const float*)d_in[13]};
    const float* bsrc[7] = {(const float*)d_in[2], (const float*)d_in[4],
                            (const float*)d_in[6], (const float*)d_in[8],
                            (const float*)d_in[10], (const float*)d_in[12],
                            (const float*)d_in[14]};
    float* out = (float*)d_out;

    float *Qb, *Kb, *Vb;
    __half *Ahi, *Alo, *Whi, *Wlo;
    cudaGetSymbolAddress((void**)&Qb, g_q);
    cudaGetSymbolAddress((void**)&Kb, g_k);
    cudaGetSymbolAddress((void**)&Vb, g_v);
    cudaGetSymbolAddress((void**)&Ahi, g_ahi);
    cudaGetSymbolAddress((void**)&Alo, g_alo);
    cudaGetSymbolAddress((void**)&Whi, g_whi);
    cudaGetSymbolAddress((void**)&Wlo, g_wlo);

    cudaFuncSetAttribute(gemm_kernel, cudaFuncAttributeMaxDynamicSharedMemorySize, GSMEM_BYTES);
    cudaFuncSetAttribute(attn2_kernel, cudaFuncAttributeMaxDynamicSharedMemorySize, ASMEM_BYTES);

    // one fused split launch (weights + activations)
    split_all_kernel<<<WSPLIT_BLOCKS + TOKENS * DIM / 4 / 256, 256>>>(
        x, wsrc[0], wsrc[1], wsrc[2], wsrc[3], wsrc[4], wsrc[5], wsrc[6],
        Ahi, Alo, Whi, Wlo);

    dim3 ggrid(DIM / 128, TOKENS / 128);
    // stage 1 projections
    gemm_kernel<<<ggrid, 256, GSMEM_BYTES>>>(Ahi, Alo, Whi + 0 * DIM * DIM, Wlo + 0 * DIM * DIM, bsrc[0], Qb);
    gemm_kernel<<<ggrid, 256, GSMEM_BYTES>>>(Ahi, Alo, Whi + 1 * DIM * DIM, Wlo + 1 * DIM * DIM, bsrc[1], Kb);
    gemm_kernel<<<ggrid, 256, GSMEM_BYTES>>>(Ahi, Alo, Whi + 2 * DIM * DIM, Wlo + 2 * DIM * DIM, bsrc[2], Vb);
    // stage 1 attention (stride 8), writes split input for stage 2
    attn2_kernel<<<4096, 128, ASMEM_BYTES>>>(Qb, Kb, Vb, Ahi, Alo, 8, 256);
    // stage 2 projections (first of these is ncu's -s 5 target)
    gemm_kernel<<<ggrid, 256, GSMEM_BYTES>>>(Ahi, Alo, Whi + 3 * DIM * DIM, Wlo + 3 * DIM * DIM, bsrc[3], Qb);
    gemm_kernel<<<ggrid, 256, GSMEM_BYTES>>>(Ahi, Alo, Whi + 4 * DIM * DIM, Wlo + 4 * DIM * DIM, bsrc[4], Kb);
    gemm_kernel<<<ggrid, 256, GSMEM_BYTES>>>(Ahi, Alo, Whi + 5 * DIM * DIM, Wlo + 5 * DIM * DIM, bsrc[5], Vb);
    // stage 2 attention (stride 256)
    attn2_kernel<<<4096, 128, ASMEM_BYTES>>>(Qb, Kb, Vb, Ahi, Alo, 256, 8);
    // output projection -> d_out
    gemm_kernel<<<ggrid, 256, GSMEM_BYTES>>>(Ahi, Alo, Whi + 6 * DIM * DIM, Wlo + 6 * DIM * DIM, bsrc[6], out);
}